// round 8
// baseline (speedup 1.0000x reference)
#include <cuda_runtime.h>
#include <cuda_fp16.h>
#include <cstdint>

// ---------------------------------------------------------------------------
// Problem constants
// ---------------------------------------------------------------------------
#define M_TOTAL 8192
#define N_TOTAL 4096
#define K_TOTAL 4096

#define TILE_M 256
#define TILE_N 128
#define KB64 64                      // granularity of pre-packed blocks
#define KTILES64 (K_TOTAL / KB64)    // 64 blocks in K
#define ITERS (KTILES64 / 2)         // 32 mainloop iterations (K=128 each)
#define STAGES 2
#define THREADS 256                  // 8 warps, warp tile 64x64
#define N_TILES (N_TOTAL / TILE_N)   // 32
#define M_TILES (M_TOTAL / TILE_M)   // 32
#define TOTAL_TILES (M_TILES * N_TILES)  // 1024
#define GROUP_M 8
#define GRID 148                     // persistent CTAs

#define A_BLK_BYTES (TILE_M * 128)              // 32KB per (m_tile, kt64)
#define B_BLK_BYTES (TILE_N * 128)              // 16KB per (n_tile, kt64)
#define STAGE_BYTES (2 * A_BLK_BYTES + 2 * B_BLK_BYTES) // 96KB (K=128)
#define SMEM_DYN (STAGES * STAGE_BYTES)         // 192KB

// ---------------------------------------------------------------------------
// Scratch: pre-converted fp16 operands, TILE-MAJOR + PRE-SWIZZLED.
// ---------------------------------------------------------------------------
__device__ __half g_xh[(size_t)M_TOTAL * K_TOTAL];   // 67 MB
__device__ __half g_wh[(size_t)N_TOTAL * K_TOTAL];   // 33.5 MB

// ---------------------------------------------------------------------------
// Helpers
// ---------------------------------------------------------------------------
__device__ __forceinline__ uint32_t smem_u32(const void* p) {
    uint32_t a;
    asm("{ .reg .u64 t; cvta.to.shared.u64 t, %1; cvt.u32.u64 %0, t; }"
        : "=r"(a) : "l"(p));
    return a;
}

__device__ __forceinline__ uint32_t sw128(uint32_t off) {
    return off ^ ((off >> 3) & 0x70);
}

__device__ __forceinline__ void mbar_init(uint32_t mbar, uint32_t cnt) {
    asm volatile("mbarrier.init.shared::cta.b64 [%0], %1;"
                 :: "r"(mbar), "r"(cnt) : "memory");
}

__device__ __forceinline__ void mbar_expect_tx(uint32_t mbar, uint32_t tx) {
    asm volatile("mbarrier.arrive.expect_tx.shared::cta.b64 _, [%0], %1;"
                 :: "r"(mbar), "r"(tx) : "memory");
}

__device__ __forceinline__ void mbar_wait(uint32_t mbar, uint32_t parity) {
    asm volatile(
        "{\n\t"
        ".reg .pred P;\n\t"
        "WAIT_%=:\n\t"
        "mbarrier.try_wait.parity.acquire.cta.shared::cta.b64 P, [%0], %1, 0x989680;\n\t"
        "@P bra.uni DONE_%=;\n\t"
        "bra.uni WAIT_%=;\n\t"
        "DONE_%=:\n\t"
        "}"
        :: "r"(mbar), "r"(parity) : "memory");
}

__device__ __forceinline__ void bulk_ld(uint32_t dst_smem, const void* src,
                                        uint32_t bytes, uint32_t mbar) {
    asm volatile(
        "cp.async.bulk.shared::cluster.global.mbarrier::complete_tx::bytes "
        "[%0], [%1], %2, [%3];"
        :: "r"(dst_smem), "l"(src), "r"(bytes), "r"(mbar) : "memory");
}

__device__ __forceinline__ void ldsm_x4(uint32_t& r0, uint32_t& r1, uint32_t& r2,
                                        uint32_t& r3, uint32_t addr) {
    asm volatile("ldmatrix.sync.aligned.m8n8.x4.shared.b16 {%0,%1,%2,%3}, [%4];"
                 : "=r"(r0), "=r"(r1), "=r"(r2), "=r"(r3) : "r"(addr));
}

__device__ __forceinline__ void mma16816(float& c0, float& c1, float& c2, float& c3,
                                         uint32_t a0, uint32_t a1, uint32_t a2,
                                         uint32_t a3, uint32_t b0, uint32_t b1) {
    asm volatile(
        "mma.sync.aligned.m16n8k16.row.col.f32.f16.f16.f32 "
        "{%0,%1,%2,%3}, {%4,%5,%6,%7}, {%8,%9}, {%0,%1,%2,%3};"
        : "+f"(c0), "+f"(c1), "+f"(c2), "+f"(c3)
        : "r"(a0), "r"(a1), "r"(a2), "r"(a3), "r"(b0), "r"(b1));
}

// ---------------------------------------------------------------------------
// Pass 1a: convert X (fp32) -> fp16, tile-major pre-swizzled layout.
// ---------------------------------------------------------------------------
__global__ void __launch_bounds__(256) cvt_x_kernel(const float* __restrict__ x) {
    size_t i = (size_t)blockIdx.x * blockDim.x + threadIdx.x;   // dst 16B chunk
    size_t n8 = (size_t)M_TOTAL * K_TOTAL / 8;
    if (i >= n8) return;
    uint32_t blk = (uint32_t)(i >> 11);          // 2048 chunks per 32KB block
    uint32_t w = (uint32_t)(i & 2047);
    uint32_t mt = blk >> 6;                      // m_tile
    uint32_t kt = blk & 63;                      // kt64
    uint32_t src_off = sw128(w * 16);            // logical byte off in block
    uint32_t r = src_off >> 7;                   // row 0..255
    uint32_t kc = (src_off & 127) >> 1;          // k within block
    size_t m = (size_t)mt * TILE_M + r;
    size_t k = (size_t)kt * KB64 + kc;
    const float4* s = reinterpret_cast<const float4*>(x + m * K_TOTAL + k);
    float4 a = s[0], b = s[1];
    __half2 h0 = __floats2half2_rn(a.x, a.y);
    __half2 h1 = __floats2half2_rn(a.z, a.w);
    __half2 h2 = __floats2half2_rn(b.x, b.y);
    __half2 h3 = __floats2half2_rn(b.z, b.w);
    uint4 o;
    o.x = reinterpret_cast<uint32_t&>(h0);
    o.y = reinterpret_cast<uint32_t&>(h1);
    o.z = reinterpret_cast<uint32_t&>(h2);
    o.w = reinterpret_cast<uint32_t&>(h3);
    reinterpret_cast<uint4*>(g_xh)[i] = o;
}

// ---------------------------------------------------------------------------
// Pass 1b: dequantize W -> fp16, tile-major pre-swizzled layout.
// ---------------------------------------------------------------------------
__global__ void __launch_bounds__(256) cvt_w_kernel(const int* __restrict__ qw,
                                                    const float* __restrict__ scales) {
    size_t i = (size_t)blockIdx.x * blockDim.x + threadIdx.x;   // dst 16B chunk
    size_t n8 = (size_t)N_TOTAL * K_TOTAL / 8;
    if (i >= n8) return;
    uint32_t blk = (uint32_t)(i >> 10);          // 1024 chunks per 16KB block
    uint32_t w = (uint32_t)(i & 1023);
    uint32_t nt = blk >> 6;                      // n_tile
    uint32_t kt = blk & 63;                      // kt64
    uint32_t src_off = sw128(w * 16);
    uint32_t r = src_off >> 7;                   // row 0..127
    uint32_t kc = (src_off & 127) >> 1;          // k within block
    size_t n = (size_t)nt * TILE_N + r;
    size_t k = (size_t)kt * KB64 + kc;
    float sc = __ldg(scales + (n * 64 + kt));
    const int4* s = reinterpret_cast<const int4*>(qw + n * K_TOTAL + k);
    int4 q0 = s[0], q1 = s[1];
    __half2 h0 = __floats2half2_rn((float)q0.x * sc, (float)q0.y * sc);
    __half2 h1 = __floats2half2_rn((float)q0.z * sc, (float)q0.w * sc);
    __half2 h2 = __floats2half2_rn((float)q1.x * sc, (float)q1.y * sc);
    __half2 h3 = __floats2half2_rn((float)q1.z * sc, (float)q1.w * sc);
    uint4 o;
    o.x = reinterpret_cast<uint32_t&>(h0);
    o.y = reinterpret_cast<uint32_t&>(h1);
    o.z = reinterpret_cast<uint32_t&>(h2);
    o.w = reinterpret_cast<uint32_t&>(h3);
    reinterpret_cast<uint4*>(g_wh)[i] = o;
}

// ---------------------------------------------------------------------------
// Pass 2: persistent HMMA GEMM with register double-buffered fragments.
//   CTA tile 256x128, 8 warps (warp tile 64x64), 2-stage K=128 TMA pipeline.
//   Slab (K=128) = 8 flattened k16 steps; frags for step s+1 are LDSM'd
//   before the 32 MMAs of step s, hiding LDS latency under MMA issue.
// ---------------------------------------------------------------------------
__global__ void __launch_bounds__(THREADS, 1) gemm_kernel(const float* __restrict__ bias,
                                                          float* __restrict__ out) {
    extern __shared__ __align__(1024) char smem[];
    __shared__ __align__(8) uint64_t mbars[STAGES];
    uint32_t sb = smem_u32(smem);
    uint32_t mb = smem_u32(mbars);

    int tid = threadIdx.x;
    int wid = tid >> 5;          // 0..7
    int lane = tid & 31;
    int warp_m = wid & 3;        // 4 warps in M (64 rows each)
    int warp_n = wid >> 2;       // 2 warps in N (64 cols each)

    if (tid == 0) {
#pragma unroll
        for (int s = 0; s < STAGES; ++s) mbar_init(mb + 8 * s, 1);
    }
    __syncthreads();

    auto tile_ptrs = [&](int t, const char*& Ab, const char*& Bb, int& mt, int& nt) {
        int group = t / (GROUP_M * N_TILES);
        int rem = t % (GROUP_M * N_TILES);
        mt = group * GROUP_M + (rem % GROUP_M);
        nt = rem / GROUP_M;
        Ab = reinterpret_cast<const char*>(g_xh) + (size_t)(mt * KTILES64) * A_BLK_BYTES;
        Bb = reinterpret_cast<const char*>(g_wh) + (size_t)(nt * KTILES64) * B_BLK_BYTES;
    };

    auto load_stage = [&](const char* Ab, const char* Bb, int it, uint32_t g) {
        uint32_t buf = g & 1;
        uint32_t m = mb + 8 * buf;
        mbar_expect_tx(m, STAGE_BYTES);
        uint32_t stage_base = sb + buf * STAGE_BYTES;
        bulk_ld(stage_base, Ab + (size_t)(2 * it) * A_BLK_BYTES, 2 * A_BLK_BYTES, m);
        bulk_ld(stage_base + 2 * A_BLK_BYTES, Bb + (size_t)(2 * it) * B_BLK_BYTES,
                2 * B_BLK_BYTES, m);
    };

    int lrow = lane & 15;        // row within 16-row block
    int lhalf = lane >> 4;       // which 8-col (k) half
    int qr = lane >> 2;          // 0..7 (epilogue)
    int qc = (lane & 3) * 2;     // 0,2,4,6 (epilogue)

    // per-warp LDSM base offsets (row part), fixed for the whole kernel
    uint32_t a_row_off[4], b_row_off[4];
#pragma unroll
    for (int mi = 0; mi < 4; ++mi)
        a_row_off[mi] = (uint32_t)((warp_m * 64 + mi * 16 + lrow) * 128 + lhalf * 16);
#pragma unroll
    for (int nh = 0; nh < 4; ++nh)
        b_row_off[nh] = (uint32_t)((warp_n * 64 + nh * 16 + lrow) * 128 + lhalf * 16);

    uint32_t g = 0;              // global stage counter (buf = g&1, parity = (g>>1)&1)

    for (int t = blockIdx.x; t < TOTAL_TILES; t += GRID) {
        const char *A0, *B0, *A1 = nullptr, *B1 = nullptr;
        int m_tile, n_tile, mt1, nt1;
        tile_ptrs(t, A0, B0, m_tile, n_tile);
        bool has_next = (t + GRID < TOTAL_TILES);
        if (has_next) tile_ptrs(t + GRID, A1, B1, mt1, nt1);

        if (t == (int)blockIdx.x && tid == 0) {   // prologue, first tile only
            load_stage(A0, B0, 0, g);
            load_stage(A0, B0, 1, g + 1);
        }

        float acc[4][8][4];
#pragma unroll
        for (int mi = 0; mi < 4; ++mi)
#pragma unroll
            for (int ni = 0; ni < 8; ++ni)
#pragma unroll
                for (int e = 0; e < 4; ++e) acc[mi][ni][e] = 0.0f;

        for (int it = 0; it < ITERS; ++it) {
            uint32_t buf = g & 1;
            mbar_wait(mb + 8 * buf, (g >> 1) & 1);
            uint32_t stage_base = sb + buf * STAGE_BYTES;

            // fragment double buffers
            uint32_t fa0[2][4], fa1[2][4], fa2[2][4], fa3[2][4];
            uint32_t fb0[2][8], fb1[2][8];

            // load frags for flattened step s into buffer pb
            auto load_frags = [&](int s, int pb) {
                int sub = s >> 2;
                int ks = s & 3;
                uint32_t abase = stage_base + sub * A_BLK_BYTES;
                uint32_t bbase = stage_base + 2 * A_BLK_BYTES + sub * B_BLK_BYTES;
                uint32_t koff = (uint32_t)(ks * 32);
#pragma unroll
                for (int mi = 0; mi < 4; ++mi)
                    ldsm_x4(fa0[pb][mi], fa1[pb][mi], fa2[pb][mi], fa3[pb][mi],
                            abase + sw128(a_row_off[mi] + koff));
#pragma unroll
                for (int nh = 0; nh < 4; ++nh) {
                    uint32_t r0, r1, r2, r3;
                    ldsm_x4(r0, r1, r2, r3, bbase + sw128(b_row_off[nh] + koff));
                    fb0[pb][nh * 2 + 0] = r0; fb1[pb][nh * 2 + 0] = r2;
                    fb0[pb][nh * 2 + 1] = r1; fb1[pb][nh * 2 + 1] = r3;
                }
            };

            load_frags(0, 0);
#pragma unroll
            for (int s = 0; s < 8; ++s) {
                int cur = s & 1;
                if (s < 7) load_frags(s + 1, cur ^ 1);   // prefetch under MMA
#pragma unroll
                for (int mi = 0; mi < 4; ++mi)
#pragma unroll
                    for (int ni = 0; ni < 8; ++ni)
                        mma16816(acc[mi][ni][0], acc[mi][ni][1],
                                 acc[mi][ni][2], acc[mi][ni][3],
                                 fa0[cur][mi], fa1[cur][mi], fa2[cur][mi], fa3[cur][mi],
                                 fb0[cur][ni], fb1[cur][ni]);
            }

            // all warps done reading buf -> safe to re-target with TMA
            __syncthreads();
            if (tid == 0) {
                int nx = it + 2;
                if (nx < ITERS) load_stage(A0, B0, nx, g);            // same buf as g
                else if (has_next) load_stage(A1, B1, nx - ITERS, g); // next tile's stage
            }
            ++g;
        }

        // epilogue: bias add + store (next tile's TMA already in flight)
        int m_base = m_tile * TILE_M;
        int n_base = n_tile * TILE_N;
#pragma unroll
        for (int mi = 0; mi < 4; ++mi) {
            int row0 = m_base + warp_m * 64 + mi * 16 + qr;
#pragma unroll
            for (int ni = 0; ni < 8; ++ni) {
                int col = n_base + warp_n * 64 + ni * 8 + qc;
                float bx = __ldg(bias + col);
                float by = __ldg(bias + col + 1);
                float2 v0 = make_float2(acc[mi][ni][0] + bx, acc[mi][ni][1] + by);
                float2 v1 = make_float2(acc[mi][ni][2] + bx, acc[mi][ni][3] + by);
                *reinterpret_cast<float2*>(out + (size_t)row0 * N_TOTAL + col) = v0;
                *reinterpret_cast<float2*>(out + (size_t)(row0 + 8) * N_TOTAL + col) = v1;
            }
        }
    }
}

// ---------------------------------------------------------------------------
// kernel_launch
// ---------------------------------------------------------------------------
extern "C" void kernel_launch(void* const* d_in, const int* in_sizes, int n_in,
                              void* d_out, int out_size) {
    const float* x      = (const float*)d_in[0];
    const int*   qw     = (const int*)d_in[1];
    const float* scales = (const float*)d_in[2];
    const float* bias   = (const float*)d_in[3];
    float*       out    = (float*)d_out;

    cudaFuncSetAttribute(gemm_kernel, cudaFuncAttributeMaxDynamicSharedMemorySize, SMEM_DYN);

    int n8x = (int)((size_t)M_TOTAL * K_TOTAL / 8);   // 4,194,304
    int n8w = (int)((size_t)N_TOTAL * K_TOTAL / 8);   // 2,097,152
    cvt_x_kernel<<<(n8x + 255) / 256, 256>>>(x);
    cvt_w_kernel<<<(n8w + 255) / 256, 256>>>(qw, scales);
    gemm_kernel<<<GRID, THREADS, SMEM_DYN>>>(bias, out);
}

// round 9
// speedup vs baseline: 1.0199x; 1.0199x over previous
#include <cuda_runtime.h>
#include <cuda_fp16.h>
#include <cstdint>

// ---------------------------------------------------------------------------
// Problem constants
// ---------------------------------------------------------------------------
#define M_TOTAL 8192
#define N_TOTAL 4096
#define K_TOTAL 4096

#define TILE_M 256
#define TILE_N 128
#define KB64 64                      // granularity of pre-packed blocks
#define KTILES64 (K_TOTAL / KB64)    // 64 blocks in K
#define ITERS (KTILES64 / 2)         // 32 mainloop iterations (K=128 each)
#define STAGES 2
#define THREADS 256                  // 8 warps, warp tile 64x64
#define N_TILES (N_TOTAL / TILE_N)   // 32
#define M_TILES (M_TOTAL / TILE_M)   // 32
#define TOTAL_TILES (M_TILES * N_TILES)  // 1024
#define GROUP_M 8
#define GRID 148                     // persistent CTAs

#define A_BLK_BYTES (TILE_M * 128)              // 32KB per (m_tile, kt64)
#define B_BLK_BYTES (TILE_N * 128)              // 16KB per (n_tile, kt64)
#define STAGE_BYTES (2 * A_BLK_BYTES + 2 * B_BLK_BYTES) // 96KB (K=128)
#define SMEM_DYN (STAGES * STAGE_BYTES)         // 192KB

// ---------------------------------------------------------------------------
// Scratch: pre-converted fp16 operands, TILE-MAJOR + PRE-SWIZZLED.
// ---------------------------------------------------------------------------
__device__ __half g_xh[(size_t)M_TOTAL * K_TOTAL];   // 67 MB
__device__ __half g_wh[(size_t)N_TOTAL * K_TOTAL];   // 33.5 MB

// ---------------------------------------------------------------------------
// Helpers
// ---------------------------------------------------------------------------
__device__ __forceinline__ uint32_t smem_u32(const void* p) {
    uint32_t a;
    asm("{ .reg .u64 t; cvta.to.shared.u64 t, %1; cvt.u32.u64 %0, t; }"
        : "=r"(a) : "l"(p));
    return a;
}

__device__ __forceinline__ uint32_t sw128(uint32_t off) {
    return off ^ ((off >> 3) & 0x70);
}

__device__ __forceinline__ void mbar_init(uint32_t mbar, uint32_t cnt) {
    asm volatile("mbarrier.init.shared::cta.b64 [%0], %1;"
                 :: "r"(mbar), "r"(cnt) : "memory");
}

__device__ __forceinline__ void mbar_expect_tx(uint32_t mbar, uint32_t tx) {
    asm volatile("mbarrier.arrive.expect_tx.shared::cta.b64 _, [%0], %1;"
                 :: "r"(mbar), "r"(tx) : "memory");
}

__device__ __forceinline__ void mbar_arrive(uint32_t mbar) {
    asm volatile("mbarrier.arrive.shared::cta.b64 _, [%0];"
                 :: "r"(mbar) : "memory");
}

__device__ __forceinline__ void mbar_wait(uint32_t mbar, uint32_t parity) {
    asm volatile(
        "{\n\t"
        ".reg .pred P;\n\t"
        "WAIT_%=:\n\t"
        "mbarrier.try_wait.parity.acquire.cta.shared::cta.b64 P, [%0], %1, 0x989680;\n\t"
        "@P bra.uni DONE_%=;\n\t"
        "bra.uni WAIT_%=;\n\t"
        "DONE_%=:\n\t"
        "}"
        :: "r"(mbar), "r"(parity) : "memory");
}

__device__ __forceinline__ void bulk_ld(uint32_t dst_smem, const void* src,
                                        uint32_t bytes, uint32_t mbar) {
    asm volatile(
        "cp.async.bulk.shared::cluster.global.mbarrier::complete_tx::bytes "
        "[%0], [%1], %2, [%3];"
        :: "r"(dst_smem), "l"(src), "r"(bytes), "r"(mbar) : "memory");
}

__device__ __forceinline__ void ldsm_x4(uint32_t& r0, uint32_t& r1, uint32_t& r2,
                                        uint32_t& r3, uint32_t addr) {
    asm volatile("ldmatrix.sync.aligned.m8n8.x4.shared.b16 {%0,%1,%2,%3}, [%4];"
                 : "=r"(r0), "=r"(r1), "=r"(r2), "=r"(r3) : "r"(addr));
}

__device__ __forceinline__ void mma16816(float& c0, float& c1, float& c2, float& c3,
                                         uint32_t a0, uint32_t a1, uint32_t a2,
                                         uint32_t a3, uint32_t b0, uint32_t b1) {
    asm volatile(
        "mma.sync.aligned.m16n8k16.row.col.f32.f16.f16.f32 "
        "{%0,%1,%2,%3}, {%4,%5,%6,%7}, {%8,%9}, {%0,%1,%2,%3};"
        : "+f"(c0), "+f"(c1), "+f"(c2), "+f"(c3)
        : "r"(a0), "r"(a1), "r"(a2), "r"(a3), "r"(b0), "r"(b1));
}

// ---------------------------------------------------------------------------
// Pass 1 (merged): convert X (fp32->fp16) and dequantize W (int8*scale->fp16)
// into tile-major pre-swizzled blocks. One launch.
//   chunks [0, N8X)        -> X
//   chunks [N8X, N8X+N8W)  -> W
// ---------------------------------------------------------------------------
#define N8X ((size_t)M_TOTAL * K_TOTAL / 8)   // 4,194,304 16B-chunks
#define N8W ((size_t)N_TOTAL * K_TOTAL / 8)   // 2,097,152 16B-chunks

__global__ void __launch_bounds__(256) cvt_kernel(const float* __restrict__ x,
                                                  const int* __restrict__ qw,
                                                  const float* __restrict__ scales) {
    size_t i = (size_t)blockIdx.x * blockDim.x + threadIdx.x;
    if (i < N8X) {
        // ---- X path ----
        uint32_t blk = (uint32_t)(i >> 11);          // 2048 chunks per 32KB block
        uint32_t w = (uint32_t)(i & 2047);
        uint32_t mt = blk >> 6;                      // m_tile
        uint32_t kt = blk & 63;                      // kt64
        uint32_t src_off = sw128(w * 16);            // logical byte off in block
        uint32_t r = src_off >> 7;                   // row 0..255
        uint32_t kc = (src_off & 127) >> 1;          // k within block
        size_t m = (size_t)mt * TILE_M + r;
        size_t k = (size_t)kt * KB64 + kc;
        const float4* s = reinterpret_cast<const float4*>(x + m * K_TOTAL + k);
        float4 a = s[0], b = s[1];
        __half2 h0 = __floats2half2_rn(a.x, a.y);
        __half2 h1 = __floats2half2_rn(a.z, a.w);
        __half2 h2 = __floats2half2_rn(b.x, b.y);
        __half2 h3 = __floats2half2_rn(b.z, b.w);
        uint4 o;
        o.x = reinterpret_cast<uint32_t&>(h0);
        o.y = reinterpret_cast<uint32_t&>(h1);
        o.z = reinterpret_cast<uint32_t&>(h2);
        o.w = reinterpret_cast<uint32_t&>(h3);
        reinterpret_cast<uint4*>(g_xh)[i] = o;
    } else if (i < N8X + N8W) {
        // ---- W path ----
        size_t j = i - N8X;
        uint32_t blk = (uint32_t)(j >> 10);          // 1024 chunks per 16KB block
        uint32_t w = (uint32_t)(j & 1023);
        uint32_t nt = blk >> 6;                      // n_tile
        uint32_t kt = blk & 63;                      // kt64
        uint32_t src_off = sw128(w * 16);
        uint32_t r = src_off >> 7;                   // row 0..127
        uint32_t kc = (src_off & 127) >> 1;          // k within block
        size_t n = (size_t)nt * TILE_N + r;
        size_t k = (size_t)kt * KB64 + kc;
        float sc = __ldg(scales + (n * 64 + kt));
        const int4* s = reinterpret_cast<const int4*>(qw + n * K_TOTAL + k);
        int4 q0 = s[0], q1 = s[1];
        __half2 h0 = __floats2half2_rn((float)q0.x * sc, (float)q0.y * sc);
        __half2 h1 = __floats2half2_rn((float)q0.z * sc, (float)q0.w * sc);
        __half2 h2 = __floats2half2_rn((float)q1.x * sc, (float)q1.y * sc);
        __half2 h3 = __floats2half2_rn((float)q1.z * sc, (float)q1.w * sc);
        uint4 o;
        o.x = reinterpret_cast<uint32_t&>(h0);
        o.y = reinterpret_cast<uint32_t&>(h1);
        o.z = reinterpret_cast<uint32_t&>(h2);
        o.w = reinterpret_cast<uint32_t&>(h3);
        reinterpret_cast<uint4*>(g_wh)[j] = o;
    }
}

// ---------------------------------------------------------------------------
// Pass 2: persistent HMMA GEMM, producer/consumer mbarrier pipeline.
//   CTA tile 256x128, 8 warps (warp tile 64x64), 2-stage K=128 TMA pipeline.
//   full[buf]: TMA tx completion (count 1). empty[buf]: all 256 threads done
//   reading (count 256). No __syncthreads in the mainloop.
//   Parity math (global stage counter g, buf = g&1):
//     full wait  for stage g      -> parity (g>>1)&1
//     empty wait before issuing stage g+2 (inside iter g) -> parity (g>>1)&1
// ---------------------------------------------------------------------------
__global__ void __launch_bounds__(THREADS, 1) gemm_kernel(const float* __restrict__ bias,
                                                          float* __restrict__ out) {
    extern __shared__ __align__(1024) char smem[];
    __shared__ __align__(8) uint64_t full_mbar[STAGES];
    __shared__ __align__(8) uint64_t empty_mbar[STAGES];
    uint32_t sb = smem_u32(smem);
    uint32_t fmb = smem_u32(full_mbar);
    uint32_t emb = smem_u32(empty_mbar);

    int tid = threadIdx.x;
    int wid = tid >> 5;          // 0..7
    int lane = tid & 31;
    int warp_m = wid & 3;        // 4 warps in M (64 rows each)
    int warp_n = wid >> 2;       // 2 warps in N (64 cols each)

    if (tid == 0) {
#pragma unroll
        for (int s = 0; s < STAGES; ++s) {
            mbar_init(fmb + 8 * s, 1);
            mbar_init(emb + 8 * s, THREADS);
        }
    }
    __syncthreads();

    auto tile_ptrs = [&](int t, const char*& Ab, const char*& Bb, int& mt, int& nt) {
        int group = t / (GROUP_M * N_TILES);
        int rem = t % (GROUP_M * N_TILES);
        mt = group * GROUP_M + (rem % GROUP_M);
        nt = rem / GROUP_M;
        Ab = reinterpret_cast<const char*>(g_xh) + (size_t)(mt * KTILES64) * A_BLK_BYTES;
        Bb = reinterpret_cast<const char*>(g_wh) + (size_t)(nt * KTILES64) * B_BLK_BYTES;
    };

    auto load_stage = [&](const char* Ab, const char* Bb, int it, uint32_t gs) {
        uint32_t buf = gs & 1;
        uint32_t m = fmb + 8 * buf;
        mbar_expect_tx(m, STAGE_BYTES);
        uint32_t stage_base = sb + buf * STAGE_BYTES;
        bulk_ld(stage_base, Ab + (size_t)(2 * it) * A_BLK_BYTES, 2 * A_BLK_BYTES, m);
        bulk_ld(stage_base + 2 * A_BLK_BYTES, Bb + (size_t)(2 * it) * B_BLK_BYTES,
                2 * B_BLK_BYTES, m);
    };

    int lrow = lane & 15;        // row within 16-row block
    int lhalf = lane >> 4;       // which 8-col (k) half
    int qr = lane >> 2;          // 0..7 (epilogue)
    int qc = (lane & 3) * 2;     // 0,2,4,6 (epilogue)

    // LDSM row offsets + precomputed SW128 XOR masks (row bits 9..7 -> 6..4).
    // All stage/sub base offsets are multiples of 1024, so the mask depends
    // only on row_off and the final address is (base + row_off + koff) ^ mask.
    uint32_t a_row_off[4], a_msk[4], b_row_off[4], b_msk[4];
#pragma unroll
    for (int mi = 0; mi < 4; ++mi) {
        a_row_off[mi] = (uint32_t)((warp_m * 64 + mi * 16 + lrow) * 128 + lhalf * 16);
        a_msk[mi] = (a_row_off[mi] >> 3) & 0x70;
    }
#pragma unroll
    for (int nh = 0; nh < 4; ++nh) {
        b_row_off[nh] = (uint32_t)((warp_n * 64 + nh * 16 + lrow) * 128 + lhalf * 16);
        b_msk[nh] = (b_row_off[nh] >> 3) & 0x70;
    }

    uint32_t g = 0;              // global stage counter

    for (int t = blockIdx.x; t < TOTAL_TILES; t += GRID) {
        const char *A0, *B0, *A1 = nullptr, *B1 = nullptr;
        int m_tile, n_tile, mt1, nt1;
        tile_ptrs(t, A0, B0, m_tile, n_tile);
        bool has_next = (t + GRID < TOTAL_TILES);
        if (has_next) tile_ptrs(t + GRID, A1, B1, mt1, nt1);

        if (t == (int)blockIdx.x && tid == 0) {   // prologue, first tile only
            load_stage(A0, B0, 0, g);
            load_stage(A0, B0, 1, g + 1);
        }

        float acc[4][8][4];
#pragma unroll
        for (int mi = 0; mi < 4; ++mi)
#pragma unroll
            for (int ni = 0; ni < 8; ++ni)
#pragma unroll
                for (int e = 0; e < 4; ++e) acc[mi][ni][e] = 0.0f;

        for (int it = 0; it < ITERS; ++it) {
            uint32_t buf = g & 1;
            uint32_t par = (g >> 1) & 1;
            mbar_wait(fmb + 8 * buf, par);
            uint32_t stage_base = sb + buf * STAGE_BYTES;

#pragma unroll
            for (int sub = 0; sub < 2; ++sub) {     // two 64-K sub-blocks
                uint32_t abase = stage_base + sub * A_BLK_BYTES;
                uint32_t bbase = stage_base + 2 * A_BLK_BYTES + sub * B_BLK_BYTES;
#pragma unroll
                for (int ks = 0; ks < 4; ++ks) {    // 4 x k16 per sub-block
                    uint32_t koff = (uint32_t)(ks * 32);
                    uint32_t a0[4], a1[4], a2[4], a3[4];
#pragma unroll
                    for (int mi = 0; mi < 4; ++mi)
                        ldsm_x4(a0[mi], a1[mi], a2[mi], a3[mi],
                                (abase + a_row_off[mi] + koff) ^ a_msk[mi]);
                    uint32_t b0[8], b1[8];
#pragma unroll
                    for (int nh = 0; nh < 4; ++nh) {
                        uint32_t r0, r1, r2, r3;
                        ldsm_x4(r0, r1, r2, r3,
                                (bbase + b_row_off[nh] + koff) ^ b_msk[nh]);
                        b0[nh * 2 + 0] = r0; b1[nh * 2 + 0] = r2;
                        b0[nh * 2 + 1] = r1; b1[nh * 2 + 1] = r3;
                    }
#pragma unroll
                    for (int mi = 0; mi < 4; ++mi)
#pragma unroll
                        for (int ni = 0; ni < 8; ++ni)
                            mma16816(acc[mi][ni][0], acc[mi][ni][1],
                                     acc[mi][ni][2], acc[mi][ni][3],
                                     a0[mi], a1[mi], a2[mi], a3[mi],
                                     b0[ni], b1[ni]);
                }
            }

            // consumer: done reading buf for this stage
            mbar_arrive(emb + 8 * buf);

            // producer: wait all 256 arrivals, then re-target buf with TMA
            if (tid == 0) {
                int nx = it + 2;
                bool issue = (nx < ITERS) || has_next;
                if (issue) {
                    mbar_wait(emb + 8 * buf, par);
                    if (nx < ITERS) load_stage(A0, B0, nx, g);
                    else load_stage(A1, B1, nx - ITERS, g);
                }
            }
            ++g;
        }

        // epilogue: bias add + store (next tile's TMA already in flight)
        int m_base = m_tile * TILE_M;
        int n_base = n_tile * TILE_N;
#pragma unroll
        for (int mi = 0; mi < 4; ++mi) {
            int row0 = m_base + warp_m * 64 + mi * 16 + qr;
#pragma unroll
            for (int ni = 0; ni < 8; ++ni) {
                int col = n_base + warp_n * 64 + ni * 8 + qc;
                float bx = __ldg(bias + col);
                float by = __ldg(bias + col + 1);
                float2 v0 = make_float2(acc[mi][ni][0] + bx, acc[mi][ni][1] + by);
                float2 v1 = make_float2(acc[mi][ni][2] + bx, acc[mi][ni][3] + by);
                *reinterpret_cast<float2*>(out + (size_t)row0 * N_TOTAL + col) = v0;
                *reinterpret_cast<float2*>(out + (size_t)(row0 + 8) * N_TOTAL + col) = v1;
            }
        }
    }
}

// ---------------------------------------------------------------------------
// kernel_launch
// ---------------------------------------------------------------------------
extern "C" void kernel_launch(void* const* d_in, const int* in_sizes, int n_in,
                              void* d_out, int out_size) {
    const float* x      = (const float*)d_in[0];
    const int*   qw     = (const int*)d_in[1];
    const float* scales = (const float*)d_in[2];
    const float* bias   = (const float*)d_in[3];
    float*       out    = (float*)d_out;

    cudaFuncSetAttribute(gemm_kernel, cudaFuncAttributeMaxDynamicSharedMemorySize, SMEM_DYN);

    size_t total_chunks = N8X + N8W;                 // 6,291,456
    int blocks = (int)((total_chunks + 255) / 256);  // 24,576
    cvt_kernel<<<blocks, 256>>>(x, qw, scales);
    gemm_kernel<<<GRID, THREADS, SMEM_DYN>>>(bias, out);
}